// round 3
// baseline (speedup 1.0000x reference)
#include <cuda_runtime.h>
#include <cstdint>

// Problem constants (shapes fixed by the dataset)
#define MAX_NODES 50000
#define F_IN   32
#define F_OUT  32
#define NB     4
#define K16    (NB * NB)          // 16 basis products
#define YROW   (K16 * F_OUT)      // 512 floats per node

// Scratch: Y[n, k, o] = sum_i x_j[n,i] * W[k,i,o]   (102.4 MB, device global)
__device__ float g_Y[(size_t)MAX_NODES * YROW];

// ---------------------------------------------------------------------------
// Kernel 0: zero the output (d_out is poisoned before timing)
// ---------------------------------------------------------------------------
__global__ void zero_out_kernel(float4* __restrict__ out, int n4) {
    int i = blockIdx.x * blockDim.x + threadIdx.x;
    if (i < n4) out[i] = make_float4(0.f, 0.f, 0.f, 0.f);
}

// ---------------------------------------------------------------------------
// Kernel 1: Y = X @ W   ([N,32] x [16,32,32] -> [N,16,32])
// 128 threads/block: thread t owns (k = t>>3, og = (t&7)*4) -> 4 consecutive
// outputs of one k-slice. W (64 KB) lives in dynamic smem; each block
// grid-strides over tiles of 8 nodes, x tile staged in smem (broadcast reads).
// ---------------------------------------------------------------------------
#define NPB 8  // nodes per tile

__global__ __launch_bounds__(128, 3) void build_Y_kernel(
    const float* __restrict__ x,       // [N, 32]
    const float* __restrict__ w,       // [16, 32, 32]
    int n_nodes)
{
    extern __shared__ float smem[];
    float* Wsh = smem;                          // 16*32*32 floats = 64 KB
    float (*xs)[F_IN] = (float (*)[F_IN])(smem + K16 * F_IN * F_OUT);

    // Stage W
    for (int idx = threadIdx.x; idx < K16 * F_IN * F_OUT; idx += blockDim.x)
        Wsh[idx] = w[idx];
    __syncthreads();

    const int k  = threadIdx.x >> 3;
    const int og = (threadIdx.x & 7) * 4;
    const float* Wk = &Wsh[k * (F_IN * F_OUT) + og];

    for (int n0 = blockIdx.x * NPB; n0 < n_nodes; n0 += gridDim.x * NPB) {
        __syncthreads();  // protect xs from previous tile
        // Stage x tile: NPB*32 = 256 floats, coalesced
        for (int idx = threadIdx.x; idx < NPB * F_IN; idx += blockDim.x) {
            int n = idx >> 5, i = idx & 31;
            int gn = n0 + n;
            xs[n][i] = (gn < n_nodes) ? x[gn * F_IN + i] : 0.f;
        }
        __syncthreads();

        float4 acc[NPB];
        #pragma unroll
        for (int n = 0; n < NPB; n++) acc[n] = make_float4(0.f, 0.f, 0.f, 0.f);

        #pragma unroll
        for (int i = 0; i < F_IN; i++) {
            float4 wv = *(const float4*)&Wk[i * F_OUT];   // conflict-free LDS.128
            #pragma unroll
            for (int n = 0; n < NPB; n++) {
                float xv = xs[n][i];                      // smem broadcast
                acc[n].x = fmaf(xv, wv.x, acc[n].x);
                acc[n].y = fmaf(xv, wv.y, acc[n].y);
                acc[n].z = fmaf(xv, wv.z, acc[n].z);
                acc[n].w = fmaf(xv, wv.w, acc[n].w);
            }
        }

        #pragma unroll
        for (int n = 0; n < NPB; n++) {
            int gn = n0 + n;
            if (gn < n_nodes)
                *(float4*)&g_Y[(size_t)gn * YROW + k * F_OUT + og] = acc[n];
        }
    }
}

// ---------------------------------------------------------------------------
// Kernel 2: per-edge bilinear gather from Y + fp32 atomic scatter to out.
// One warp per edge, lane = output channel o.
// Hat basis on [-1,1] with 4 centers: only 2 adjacent centers are nonzero per
// dim -> 4 (kx,ky) corners with bilinear coefficients.
// ---------------------------------------------------------------------------
__global__ __launch_bounds__(256) void edge_msg_kernel(
    const int*   __restrict__ ei,   // [2, E] : row0 = dst, row1 = src
    const float* __restrict__ ea,   // [E, 2]
    float*       __restrict__ out,  // [N, 32]
    int E)
{
    const int lane = threadIdx.x & 31;
    const int e = (blockIdx.x * blockDim.x + threadIdx.x) >> 5;
    if (e >= E) return;

    const int dst = ei[e];
    const int src = ei[E + e];
    const float ax = ea[2 * e];
    const float ay = ea[2 * e + 1];

    // u = (x+1)/dx in [0,3]; cell j = floor(u) clamped to [0,2]; t = u - j
    float ux = fminf(fmaxf((ax + 1.0f) * 1.5f, 0.0f), 3.0f);
    float uy = fminf(fmaxf((ay + 1.0f) * 1.5f, 0.0f), 3.0f);
    int jx = min((int)ux, 2);
    int jy = min((int)uy, 2);
    float tx = ux - (float)jx;
    float ty = uy - (float)jy;
    float sx = 1.0f - tx, sy = 1.0f - ty;

    // k = kx*4 + ky ; corner (jx,jy): +32 per ky step, +128 per kx step
    const float* Yp = &g_Y[(size_t)src * YROW + (jx * NB + jy) * F_OUT + lane];
    float m = sx * (sy * Yp[0]   + ty * Yp[32])
            + tx * (sy * Yp[128] + ty * Yp[160]);

    atomicAdd(out + dst * F_OUT + lane, m);
}

// ---------------------------------------------------------------------------
// Launch
// Inputs (metadata order): x_i, x_j, edge_index, edge_attr, weight
// ---------------------------------------------------------------------------
extern "C" void kernel_launch(void* const* d_in, const int* in_sizes, int n_in,
                              void* d_out, int out_size)
{
    const float* x_j = (const float*)d_in[1];
    const int*   ei  = (const int*)  d_in[2];
    const float* ea  = (const float*)d_in[3];
    const float* w   = (const float*)d_in[4];
    float* out = (float*)d_out;

    const int n_nodes = in_sizes[0] / F_IN;
    const int E       = in_sizes[2] / 2;

    // K0: zero output
    {
        int n4 = out_size / 4;
        zero_out_kernel<<<(n4 + 255) / 256, 256>>>((float4*)d_out, n4);
    }

    // K1: build Y  (dynamic smem: 64 KB W + x tile)
    {
        static const int smem_bytes = (K16 * F_IN * F_OUT + NPB * F_IN) * (int)sizeof(float);
        cudaFuncSetAttribute(build_Y_kernel,
                             cudaFuncAttributeMaxDynamicSharedMemorySize, smem_bytes);
        build_Y_kernel<<<444, 128, smem_bytes>>>(x_j, w, n_nodes);
    }

    // K2: edge gather + scatter (one warp per edge)
    {
        int warps_per_block = 256 / 32;
        int blocks = (E + warps_per_block - 1) / warps_per_block;
        edge_msg_kernel<<<blocks, 256>>>(ei, ea, out, E);
    }

    (void)n_in; (void)out;
}